// round 2
// baseline (speedup 1.0000x reference)
#include <cuda_runtime.h>
#include <cstdint>

typedef unsigned long long ull;

#define D1 270
#define KK 32
#define CC 60
#define BB 64
#define TT 4096
#define KL (KK*KK)        // 1024

// ---------------- scratch (no allocs allowed) ----------------
__device__ float g_cos[KL * CC];   // [kl][c]
__device__ float g_sin[KL * CC];
__device__ float g_w[D1 * CC];     // [j][c]

// ---------------- f32x2 helpers ----------------
__device__ __forceinline__ ull fma2(ull a, ull b, ull c) {
    ull d;
    asm("fma.rn.f32x2 %0, %1, %2, %3;" : "=l"(d) : "l"(a), "l"(b), "l"(c));
    return d;
}
__device__ __forceinline__ ull pack2(float lo, float hi) {
    ull d;
    asm("mov.b64 %0, {%1, %2};" : "=l"(d) : "f"(lo), "f"(hi));
    return d;
}
__device__ __forceinline__ float2 unpack2(ull v) {
    float lo, hi;
    asm("mov.b64 {%0, %1}, %2;" : "=f"(lo), "=f"(hi) : "l"(v));
    return make_float2(lo, hi);
}

// ---------------- K1: sin/cos tables ----------------
__global__ void k_tables(const float* __restrict__ loc) {
    int idx = blockIdx.x * blockDim.x + threadIdx.x;
    if (idx >= KL * CC) return;
    int kl = idx / CC;
    int c  = idx - kl * CC;
    int k = kl >> 5, l = kl & 31;
    float t = (float)k * loc[2 * c] + (float)l * loc[2 * c + 1];
    float s, co;
    sincosf(6.283185307179586f * t, &s, &co);
    g_cos[idx] = co;
    g_sin[idx] = s;
}

// ---------------- K2: a[j,c] + softmax over c -> g_w ----------------
__global__ void k_weights(const float* __restrict__ z_re,
                          const float* __restrict__ z_im) {
    int j   = blockIdx.x;
    int tid = threadIdx.x;          // 256 threads
    int c   = tid & 63;
    int s   = tid >> 6;             // 4 kl-slices

    float partial = 0.f;
    if (c < CC) {
        const float* zr = z_re + j * KL;
        const float* zi = z_im + j * KL;
        for (int kl = s; kl < KL; kl += 4) {
            partial += zr[kl] * g_cos[kl * CC + c] + zi[kl] * g_sin[kl * CC + c];
        }
    }
    __shared__ float sp[4][64];
    __shared__ float aval[64];
    __shared__ float red[2];
    sp[s][c] = partial;
    __syncthreads();
    if (tid < 64) {
        aval[tid] = sp[0][tid] + sp[1][tid] + sp[2][tid] + sp[3][tid];
    }
    __syncthreads();
    if (tid == 0) {
        float m = -1e30f;
        for (int i = 0; i < CC; i++) m = fmaxf(m, aval[i]);
        float ssum = 0.f;
        for (int i = 0; i < CC; i++) ssum += expf(aval[i] - m);
        red[0] = m;
        red[1] = ssum;
    }
    __syncthreads();
    if (tid < CC) {
        g_w[j * CC + tid] = expf(aval[tid] - red[0]) / red[1];
    }
}

// ---------------- K3: out[b,j,t] = sum_c w[j,c] * X[b,c,t] ----------------
// Block: 256 threads = 64 t-quads x 4 j-groups; t-tile = 256, all 270 j in 12 iters.
// Smem: Xs[60][256] + ws[60][32] (w padded, stride 8 per jg for vector LDS)
#define SMEM3 (CC * 256 * 4 + CC * 32 * 4)   // 61440 + 7680 = 69120 B

__global__ __launch_bounds__(256) void k_mix(const float* __restrict__ X,
                                             float* __restrict__ out) {
    extern __shared__ float sm[];
    float* Xs = sm;                 // [c][256]
    float* ws = sm + CC * 256;      // [c][32]: slot = c*32 + jg*8 + r

    int b   = blockIdx.y;
    int t0  = blockIdx.x * 256;
    int tid = threadIdx.x;
    int tq  = tid & 63;             // t-quad: t = t0 + tq*4
    int jg  = tid >> 6;             // 0..3

    // stage X[b, 0:60, t0:t0+256] (read from DRAM exactly once)
    const float* Xb = X + (size_t)b * CC * TT + t0;
    for (int i = tid; i < CC * 64; i += 256) {
        int c = i >> 6, q = i & 63;
        *(float4*)&Xs[c * 256 + q * 4] = *(const float4*)&Xb[(size_t)c * TT + q * 4];
    }

    float* outb = out + (size_t)b * D1 * TT + t0 + tq * 4;

    for (int iter = 0; iter < 12; iter++) {
        int jbase = iter * 24;
        __syncthreads();   // protect ws (and Xs on iter 0)
        for (int i = tid; i < 24 * CC; i += 256) {
            int r = i / CC, c = i - r * CC;
            int j = jbase + r;
            if (j > D1 - 1) j = D1 - 1;          // clamp (last iter partial)
            ws[c * 32 + (r / 6) * 8 + (r % 6)] = g_w[j * CC + c];
        }
        __syncthreads();

        ull acc[6][2];
#pragma unroll
        for (int r = 0; r < 6; r++) { acc[r][0] = 0ull; acc[r][1] = 0ull; }

#pragma unroll 5
        for (int c = 0; c < CC; c++) {
            float4 xv = *(const float4*)&Xs[c * 256 + tq * 4];
            ull xlo = pack2(xv.x, xv.y);
            ull xhi = pack2(xv.z, xv.w);
            const float* wp = &ws[c * 32 + jg * 8];
            float4 wa = *(const float4*)wp;
            float2 wb = *(const float2*)(wp + 4);
            float wv[6] = {wa.x, wa.y, wa.z, wa.w, wb.x, wb.y};
#pragma unroll
            for (int r = 0; r < 6; r++) {
                ull wpk = pack2(wv[r], wv[r]);
                acc[r][0] = fma2(xlo, wpk, acc[r][0]);
                acc[r][1] = fma2(xhi, wpk, acc[r][1]);
            }
        }

#pragma unroll
        for (int r = 0; r < 6; r++) {
            int j = jbase + jg * 6 + r;
            if (j < D1) {
                float2 lo = unpack2(acc[r][0]);
                float2 hi = unpack2(acc[r][1]);
                float4 o = make_float4(lo.x, lo.y, hi.x, hi.y);
                *(float4*)&outb[(size_t)j * TT] = o;
            }
        }
    }
}

// ---------------- launch ----------------
extern "C" void kernel_launch(void* const* d_in, const int* in_sizes, int n_in,
                              void* d_out, int out_size) {
    const float* X    = (const float*)d_in[0];
    const float* z_re = (const float*)d_in[1];
    const float* z_im = (const float*)d_in[2];
    const float* loc  = (const float*)d_in[3];
    float* out = (float*)d_out;

    k_tables<<<(KL * CC + 255) / 256, 256>>>(loc);
    k_weights<<<D1, 256>>>(z_re, z_im);

    cudaFuncSetAttribute(k_mix, cudaFuncAttributeMaxDynamicSharedMemorySize, SMEM3);
    k_mix<<<dim3(TT / 256, BB), 256, SMEM3>>>(X, out);
}